// round 14
// baseline (speedup 1.0000x reference)
#include <cuda_runtime.h>

#define DIM 16
#define TILE_ROWS 512
#define ROW_WORDS 20            /* 16 data floats + 4 pad -> 80B row stride */
#define TILE_WORDS (TILE_ROWS * ROW_WORDS)

// Folded weights: out = chem @ M^T + c, where M = Wo @ Wv, c = Wo @ bv + bo
__device__ __align__(16) float g_M[DIM * DIM];  // M[j][i], row-major
__device__ __align__(16) float g_c[DIM];

// ---------------------------------------------------------------------------
// Tiny prep kernel: fold the two 16x16 matmuls + biases into one matrix.
// ---------------------------------------------------------------------------
__global__ void prep_kernel(const float* __restrict__ in_w,   // [48,16]
                            const float* __restrict__ in_b,   // [48]
                            const float* __restrict__ out_w,  // [16,16]
                            const float* __restrict__ out_b)  // [16]
{
    const int t = threadIdx.x;           // 0..255
    const int j = t >> 4;
    const int i = t & 15;
    float s = 0.f;
#pragma unroll
    for (int k = 0; k < DIM; ++k)
        s += out_w[j * DIM + k] * in_w[(2 * DIM + k) * DIM + i];
    g_M[j * DIM + i] = s;
    if (i == 0) {
        float c = out_b[j];
#pragma unroll
        for (int k = 0; k < DIM; ++k)
            c += out_w[j * DIM + k] * in_b[2 * DIM + k];
        g_c[j] = c;
    }
}

// packed f32x2 FMA (Blackwell; only reachable via PTX)
__device__ __forceinline__ unsigned long long ffma2(unsigned long long a,
                                                    unsigned long long b,
                                                    unsigned long long c)
{
    unsigned long long d;
    asm("fma.rn.f32x2 %0, %1, %2, %3;" : "=l"(d) : "l"(a), "l"(b), "l"(c));
    return d;
}

// ---------------------------------------------------------------------------
// Two-phase tile kernel.
//  Phase 1: cp.async.cg stages a 512-row tile (32KB of data) into smem with
//           perfectly coalesced 512B-per-warp-instruction loads (128B/wf).
//           Rows are padded to 80B so the compute phase is bank-conflict-free.
//  Phase 2: 4 threads/row x 4 output cols/thread (weights in 64 regs),
//           inputs read from smem (broadcast within each 4-lane group, the
//           8 row addresses per warp hit 8 distinct bank groups).
// ---------------------------------------------------------------------------
__global__ void __launch_bounds__(256, 2)
matvec_kernel(const float* __restrict__ chem, float* __restrict__ out, int rows)
{
    __shared__ __align__(16) float tile[TILE_WORDS];

    const int tid = threadIdx.x;
    const size_t row_base = (size_t)blockIdx.x * TILE_ROWS;

    // ---- Phase 1: stage tile into smem via cp.async ----
    {
        const char* gbase =
            reinterpret_cast<const char*>(chem + row_base * DIM);
#pragma unroll
        for (int k = 0; k < 8; ++k) {
            const int c   = tid + k * 256;        // 16B chunk index, 0..2047
            const int r   = c >> 2;               // row within tile
            const int sub = c & 3;                // 16B chunk within row
            const unsigned smem_addr = (unsigned)
                __cvta_generic_to_shared(&tile[r * ROW_WORDS + sub * 4]);
            const char* gptr = gbase + (size_t)c * 16;
            asm volatile("cp.async.cg.shared.global [%0], [%1], 16;\n"
                         :: "r"(smem_addr), "l"(gptr));
        }
        asm volatile("cp.async.commit_group;\n");
    }

    // ---- Load weights while the tile is in flight ----
    const int e  = tid & 3;            // 4 threads per row
    const int jg = e * 4;              // first of this thread's 4 output cols
    unsigned long long w[4][8];
    float c4[4];
#pragma unroll
    for (int j = 0; j < 4; ++j) {
        const unsigned long long* wp =
            reinterpret_cast<const unsigned long long*>(&g_M[(jg + j) * DIM]);
#pragma unroll
        for (int i2 = 0; i2 < 8; ++i2) w[j][i2] = wp[i2];
        c4[j] = g_c[jg + j];
    }

    asm volatile("cp.async.wait_group 0;\n");
    __syncthreads();

    // ---- Phase 2: compute. 64 rows per pass, 8 passes cover 512 rows ----
    const int r0 = tid >> 2;           // this thread's row within the pass
#pragma unroll
    for (int p = 0; p < 8; ++p) {
        const int r = r0 + p * 64;
        const ulonglong2* sp =
            reinterpret_cast<const ulonglong2*>(&tile[r * ROW_WORDS]);
        ulonglong2 a0 = sp[0];
        ulonglong2 a1 = sp[1];
        ulonglong2 a2 = sp[2];
        ulonglong2 a3 = sp[3];
        const unsigned long long ap[8] = {a0.x, a0.y, a1.x, a1.y,
                                          a2.x, a2.y, a3.x, a3.y};

        float4 res;
        float* rp = reinterpret_cast<float*>(&res);
#pragma unroll
        for (int j = 0; j < 4; ++j) {
            unsigned long long acc =
                (unsigned long long)__float_as_uint(c4[j]);
#pragma unroll
            for (int i2 = 0; i2 < 8; ++i2)
                acc = ffma2(ap[i2], w[j][i2], acc);
            rp[j] = __uint_as_float((unsigned int)acc) +
                    __uint_as_float((unsigned int)(acc >> 32));
        }

        // warp store: lanes cover 8 consecutive rows x 64B = 512B contiguous
        reinterpret_cast<float4*>(out + (row_base + r) * DIM)[e] = res;
    }
}

extern "C" void kernel_launch(void* const* d_in, const int* in_sizes, int n_in,
                              void* d_out, int out_size)
{
    // inputs: 0=fp_16 (UNUSED), 1=chem_16, 2=in_proj_weight, 3=in_proj_bias,
    //         4=out_proj_weight, 5=out_proj_bias
    const float* chem  = (const float*)d_in[1];
    const float* in_w  = (const float*)d_in[2];
    const float* in_b  = (const float*)d_in[3];
    const float* out_w = (const float*)d_in[4];
    const float* out_b = (const float*)d_in[5];
    float* out = (float*)d_out;

    const int rows = in_sizes[1] / DIM;   // 2,097,152 (divisible by 512)

    prep_kernel<<<1, 256>>>(in_w, in_b, out_w, out_b);

    const int blocks = rows / TILE_ROWS;  // 4096 one-tile blocks
    matvec_kernel<<<blocks, 256>>>(chem, out, rows);
}

// round 15
// speedup vs baseline: 1.2449x; 1.2449x over previous
#include <cuda_runtime.h>

#define DIM 16
#define TROWS 256                 /* rows per tile */
#define ROW_WORDS 20              /* 16 data floats + 4 pad -> 80B stride   */
#define TWORDS (TROWS * ROW_WORDS)/* 5120 words = 20KB per buffer           */
#define TILES_PER_BLOCK 8

// Folded weights: out = chem @ M^T + c, where M = Wo @ Wv, c = Wo @ bv + bo
__device__ __align__(16) float g_M[DIM * DIM];  // M[j][i], row-major
__device__ __align__(16) float g_c[DIM];

// ---------------------------------------------------------------------------
// Tiny prep kernel: fold the two 16x16 matmuls + biases into one matrix.
// ---------------------------------------------------------------------------
__global__ void prep_kernel(const float* __restrict__ in_w,   // [48,16]
                            const float* __restrict__ in_b,   // [48]
                            const float* __restrict__ out_w,  // [16,16]
                            const float* __restrict__ out_b)  // [16]
{
    const int t = threadIdx.x;           // 0..255
    const int j = t >> 4;
    const int i = t & 15;
    float s = 0.f;
#pragma unroll
    for (int k = 0; k < DIM; ++k)
        s += out_w[j * DIM + k] * in_w[(2 * DIM + k) * DIM + i];
    g_M[j * DIM + i] = s;
    if (i == 0) {
        float c = out_b[j];
#pragma unroll
        for (int k = 0; k < DIM; ++k)
            c += out_w[j * DIM + k] * in_b[2 * DIM + k];
        g_c[j] = c;
    }
}

// packed f32x2 FMA (Blackwell; only reachable via PTX)
__device__ __forceinline__ unsigned long long ffma2(unsigned long long a,
                                                    unsigned long long b,
                                                    unsigned long long c)
{
    unsigned long long d;
    asm("fma.rn.f32x2 %0, %1, %2, %3;" : "=l"(d) : "l"(a), "l"(b), "l"(c));
    return d;
}

// ---------------------------------------------------------------------------
// Double-buffered cp.async pipeline. Each block processes 8 consecutive
// 256-row tiles; the cp.async stream for tile i+1 overlaps the compute of
// tile i, so DRAM stays busy through the FMA/LDS phase (R14's full-drain
// wait_group 0 left HBM idle ~56% of the time).
// Compute: 4 threads/row x 4 output cols (weights in 64 regs), conflict-free
// smem reads (20-word row stride partitions all 32 banks).
// ---------------------------------------------------------------------------
__global__ void __launch_bounds__(256, 2)
matvec_kernel(const float* __restrict__ chem, float* __restrict__ out, int rows)
{
    __shared__ __align__(16) float tile[2][TWORDS];

    const int tid    = threadIdx.x;
    const int ntiles = rows / TROWS;          // rows is a multiple of TROWS
    int t            = blockIdx.x * TILES_PER_BLOCK;
    const int tend   = (t + TILES_PER_BLOCK < ntiles) ? t + TILES_PER_BLOCK
                                                      : ntiles;

    // ---- stage a 256-row tile into buffer b (4 cp.async.cg per thread) ----
    auto issue_load = [&](int b, int tt) {
        const char* gbase = reinterpret_cast<const char*>(chem) +
                            (size_t)tt * (TROWS * DIM * 4);
#pragma unroll
        for (int k = 0; k < 4; ++k) {
            const int c   = tid + k * 256;     // 16B chunk index, 0..1023
            const int r   = c >> 2;            // row within tile
            const int sub = c & 3;             // 16B chunk within row
            const unsigned sa = (unsigned)
                __cvta_generic_to_shared(&tile[b][r * ROW_WORDS + sub * 4]);
            asm volatile("cp.async.cg.shared.global [%0], [%1], 16;\n"
                         :: "r"(sa), "l"(gbase + (size_t)c * 16));
        }
    };

    // ---- prologue: first tile load in flight, then fetch weights ----
    if (t < tend) issue_load(0, t);
    asm volatile("cp.async.commit_group;\n");

    const int e  = tid & 3;            // 4 threads per row
    const int jg = e * 4;              // first of this thread's 4 output cols
    unsigned long long w[4][8];
    float c4[4];
#pragma unroll
    for (int j = 0; j < 4; ++j) {
        const unsigned long long* wp =
            reinterpret_cast<const unsigned long long*>(&g_M[(jg + j) * DIM]);
#pragma unroll
        for (int i2 = 0; i2 < 8; ++i2) w[j][i2] = wp[i2];
        c4[j] = g_c[jg + j];
    }

    const int r0 = tid >> 2;           // this thread's row within a pass

    int buf = 0;
    for (; t < tend; ++t, buf ^= 1) {
        // issue next tile's loads before waiting on the current one
        if (t + 1 < tend) issue_load(buf ^ 1, t + 1);
        asm volatile("cp.async.commit_group;\n");
        asm volatile("cp.async.wait_group 1;\n");   // current tile complete
        __syncthreads();

        const size_t row_base = (size_t)t * TROWS;
#pragma unroll
        for (int p = 0; p < 4; ++p) {              // 64 rows per pass
            const int r = r0 + p * 64;
            const ulonglong2* sp =
                reinterpret_cast<const ulonglong2*>(&tile[buf][r * ROW_WORDS]);
            ulonglong2 a0 = sp[0];
            ulonglong2 a1 = sp[1];
            ulonglong2 a2 = sp[2];
            ulonglong2 a3 = sp[3];
            const unsigned long long ap[8] = {a0.x, a0.y, a1.x, a1.y,
                                              a2.x, a2.y, a3.x, a3.y};

            float4 res;
            float* rp = reinterpret_cast<float*>(&res);
#pragma unroll
            for (int j = 0; j < 4; ++j) {
                unsigned long long acc =
                    (unsigned long long)__float_as_uint(c4[j]);
#pragma unroll
                for (int i2 = 0; i2 < 8; ++i2)
                    acc = ffma2(ap[i2], w[j][i2], acc);
                rp[j] = __uint_as_float((unsigned int)acc) +
                        __uint_as_float((unsigned int)(acc >> 32));
            }

            // warp store: 8 consecutive rows x 64B = 512B contiguous
            reinterpret_cast<float4*>(out + (row_base + r) * DIM)[e] = res;
        }
        __syncthreads();   // all reads of tile[buf] done before it is reloaded
    }
}

extern "C" void kernel_launch(void* const* d_in, const int* in_sizes, int n_in,
                              void* d_out, int out_size)
{
    // inputs: 0=fp_16 (UNUSED), 1=chem_16, 2=in_proj_weight, 3=in_proj_bias,
    //         4=out_proj_weight, 5=out_proj_bias
    const float* chem  = (const float*)d_in[1];
    const float* in_w  = (const float*)d_in[2];
    const float* in_b  = (const float*)d_in[3];
    const float* out_w = (const float*)d_in[4];
    const float* out_b = (const float*)d_in[5];
    float* out = (float*)d_out;

    const int rows = in_sizes[1] / DIM;   // 2,097,152 (multiple of 256*8)

    prep_kernel<<<1, 256>>>(in_w, in_b, out_w, out_b);

    const int ntiles = rows / TROWS;                       // 8192
    const int blocks = (ntiles + TILES_PER_BLOCK - 1) / TILES_PER_BLOCK; // 1024
    matvec_kernel<<<blocks, 256>>>(chem, out, rows);
}

// round 16
// speedup vs baseline: 1.3099x; 1.0523x over previous
#include <cuda_runtime.h>

#define DIM 16
#define TROWS 256                  /* rows per tile                         */
#define ROW_WORDS 20               /* 16 data floats + 4 pad -> 80B stride  */
#define TWORDS (TROWS * ROW_WORDS) /* 5120 words = 20KB per buffer          */
#define NBUF 3
#define TILES_PER_BLOCK 8
#define SMEM_BYTES (NBUF * TWORDS * 4)   /* 60KB dynamic                    */

// Folded weights: out = chem @ M^T + c, where M = Wo @ Wv, c = Wo @ bv + bo
__device__ __align__(16) float g_M[DIM * DIM];  // M[j][i], row-major
__device__ __align__(16) float g_c[DIM];

// ---------------------------------------------------------------------------
// Tiny prep kernel: fold the two 16x16 matmuls + biases into one matrix.
// ---------------------------------------------------------------------------
__global__ void prep_kernel(const float* __restrict__ in_w,   // [48,16]
                            const float* __restrict__ in_b,   // [48]
                            const float* __restrict__ out_w,  // [16,16]
                            const float* __restrict__ out_b)  // [16]
{
    const int t = threadIdx.x;           // 0..255
    const int j = t >> 4;
    const int i = t & 15;
    float s = 0.f;
#pragma unroll
    for (int k = 0; k < DIM; ++k)
        s += out_w[j * DIM + k] * in_w[(2 * DIM + k) * DIM + i];
    g_M[j * DIM + i] = s;
    if (i == 0) {
        float c = out_b[j];
#pragma unroll
        for (int k = 0; k < DIM; ++k)
            c += out_w[j * DIM + k] * in_b[2 * DIM + k];
        g_c[j] = c;
    }
}

// packed f32x2 FMA (Blackwell; only reachable via PTX)
__device__ __forceinline__ unsigned long long ffma2(unsigned long long a,
                                                    unsigned long long b,
                                                    unsigned long long c)
{
    unsigned long long d;
    asm("fma.rn.f32x2 %0, %1, %2, %3;" : "=l"(d) : "l"(a), "l"(b), "l"(c));
    return d;
}

// ---------------------------------------------------------------------------
// Triple-buffered cp.async pipeline, 8 tiles per block.
//   wait_group 2 keeps TWO tile loads streaming during each tile's compute
//   (R15's depth-2 had only one -> 32KB/SM in flight -> 4.4TB/s ceiling).
// Compute: 8 threads/row x 2 output cols (weights in 32 regs so 3 blocks/SM
//   fit), inputs from smem (4-lane address groups broadcast; 80B row stride
//   keeps the crossbar conflict-free).
// ---------------------------------------------------------------------------
__global__ void __launch_bounds__(256, 3)
matvec_kernel(const float* __restrict__ chem, float* __restrict__ out, int rows)
{
    extern __shared__ __align__(16) float tile[];   // [NBUF][TWORDS]

    const int tid    = threadIdx.x;
    const int ntiles = rows / TROWS;
    const int t0     = blockIdx.x * TILES_PER_BLOCK;
    const int tend   = (t0 + TILES_PER_BLOCK < ntiles) ? t0 + TILES_PER_BLOCK
                                                       : ntiles;

    // ---- stage a 256-row tile into buffer b (4 cp.async.cg per thread) ----
    auto issue_load = [&](int b, int tt) {
        const char* gbase = reinterpret_cast<const char*>(chem) +
                            (size_t)tt * (TROWS * DIM * 4);
        float* sbase = tile + b * TWORDS;
#pragma unroll
        for (int k = 0; k < 4; ++k) {
            const int c   = tid + k * 256;     // 16B chunk index, 0..1023
            const int r   = c >> 2;            // row within tile
            const int sub = c & 3;             // 16B chunk within row
            const unsigned sa = (unsigned)
                __cvta_generic_to_shared(&sbase[r * ROW_WORDS + sub * 4]);
            asm volatile("cp.async.cg.shared.global [%0], [%1], 16;\n"
                         :: "r"(sa), "l"(gbase + (size_t)c * 16));
        }
    };

    // ---- prologue: two tile loads in flight, then fetch weights ----
    if (t0 < tend) issue_load(0, t0);
    asm volatile("cp.async.commit_group;\n");
    if (t0 + 1 < tend) issue_load(1, t0 + 1);
    asm volatile("cp.async.commit_group;\n");

    const int e  = tid & 7;            // 8 threads per row
    const int jg = e * 2;              // this thread's 2 output columns
    unsigned long long w0[8], w1[8];
    {
        const unsigned long long* wp0 =
            reinterpret_cast<const unsigned long long*>(&g_M[(jg + 0) * DIM]);
        const unsigned long long* wp1 =
            reinterpret_cast<const unsigned long long*>(&g_M[(jg + 1) * DIM]);
#pragma unroll
        for (int i2 = 0; i2 < 8; ++i2) { w0[i2] = wp0[i2]; w1[i2] = wp1[i2]; }
    }
    const float c0 = g_c[jg + 0];
    const float c1 = g_c[jg + 1];

    const int r0 = tid >> 3;           // this thread's row within a pass

    int buf = 0;
    for (int t = t0; t < tend; ++t) {
        // keep the pipe full: issue tile t+2 (into the buffer computed at t-1)
        if (t + 2 < tend) issue_load((buf + 2) % NBUF, t + 2);
        asm volatile("cp.async.commit_group;\n");
        asm volatile("cp.async.wait_group 2;\n");   // tile t complete
        __syncthreads();

        const float* sbase = tile + buf * TWORDS;
        const size_t row_base = (size_t)t * TROWS;
#pragma unroll
        for (int p = 0; p < 8; ++p) {              // 32 rows per pass
            const int r = r0 + p * 32;
            const ulonglong2* sp =
                reinterpret_cast<const ulonglong2*>(&sbase[r * ROW_WORDS]);
            ulonglong2 a0 = sp[0];
            ulonglong2 a1 = sp[1];
            ulonglong2 a2 = sp[2];
            ulonglong2 a3 = sp[3];
            const unsigned long long ap[8] = {a0.x, a0.y, a1.x, a1.y,
                                              a2.x, a2.y, a3.x, a3.y};

            unsigned long long acc0 =
                (unsigned long long)__float_as_uint(c0);
            unsigned long long acc1 =
                (unsigned long long)__float_as_uint(c1);
#pragma unroll
            for (int i2 = 0; i2 < 8; ++i2) {
                acc0 = ffma2(ap[i2], w0[i2], acc0);
                acc1 = ffma2(ap[i2], w1[i2], acc1);
            }
            float2 res;
            res.x = __uint_as_float((unsigned int)acc0) +
                    __uint_as_float((unsigned int)(acc0 >> 32));
            res.y = __uint_as_float((unsigned int)acc1) +
                    __uint_as_float((unsigned int)(acc1 >> 32));

            // warp store: 4 consecutive rows x 64B = 256B contiguous
            reinterpret_cast<float2*>(out + (row_base + r) * DIM)[e] = res;
        }
        __syncthreads();   // tile[buf] fully read before t+? reloads it
        buf = (buf + 1) % NBUF;
    }
}

extern "C" void kernel_launch(void* const* d_in, const int* in_sizes, int n_in,
                              void* d_out, int out_size)
{
    // inputs: 0=fp_16 (UNUSED), 1=chem_16, 2=in_proj_weight, 3=in_proj_bias,
    //         4=out_proj_weight, 5=out_proj_bias
    const float* chem  = (const float*)d_in[1];
    const float* in_w  = (const float*)d_in[2];
    const float* in_b  = (const float*)d_in[3];
    const float* out_w = (const float*)d_in[4];
    const float* out_b = (const float*)d_in[5];
    float* out = (float*)d_out;

    const int rows = in_sizes[1] / DIM;   // 2,097,152 (multiple of 256*8)

    static bool attr_set = false;
    if (!attr_set) {
        cudaFuncSetAttribute(matvec_kernel,
                             cudaFuncAttributeMaxDynamicSharedMemorySize,
                             SMEM_BYTES);
        attr_set = true;
    }

    prep_kernel<<<1, 256>>>(in_w, in_b, out_w, out_b);

    const int ntiles = rows / TROWS;                                   // 8192
    const int blocks = (ntiles + TILES_PER_BLOCK - 1) / TILES_PER_BLOCK; // 1024
    matvec_kernel<<<blocks, 256, SMEM_BYTES>>>(chem, out, rows);
}

// round 17
// speedup vs baseline: 1.3496x; 1.0303x over previous
#include <cuda_runtime.h>

#define DIM 16
#define TROWS_W 32                      /* rows per warp-tile               */
#define ROW_WORDS 20                    /* 16 data + 4 pad -> 80B stride    */
#define TWORDS_W (TROWS_W * ROW_WORDS)  /* 640 words = 2560B per buffer     */
#define NBUF 3
#define TILES_PER_WARP 8
#define WARPS_PER_BLOCK 8
#define SMEM_BYTES (WARPS_PER_BLOCK * NBUF * TWORDS_W * 4)   /* 61440B */

// Folded weights: out = chem @ M^T + c, where M = Wo @ Wv, c = Wo @ bv + bo
__device__ __align__(16) float g_M[DIM * DIM];  // M[j][i], row-major
__device__ __align__(16) float g_c[DIM];

// ---------------------------------------------------------------------------
// Tiny prep kernel: fold the two 16x16 matmuls + biases into one matrix.
// ---------------------------------------------------------------------------
__global__ void prep_kernel(const float* __restrict__ in_w,   // [48,16]
                            const float* __restrict__ in_b,   // [48]
                            const float* __restrict__ out_w,  // [16,16]
                            const float* __restrict__ out_b)  // [16]
{
    const int t = threadIdx.x;           // 0..255
    const int j = t >> 4;
    const int i = t & 15;
    float s = 0.f;
#pragma unroll
    for (int k = 0; k < DIM; ++k)
        s += out_w[j * DIM + k] * in_w[(2 * DIM + k) * DIM + i];
    g_M[j * DIM + i] = s;
    if (i == 0) {
        float c = out_b[j];
#pragma unroll
        for (int k = 0; k < DIM; ++k)
            c += out_w[j * DIM + k] * in_b[2 * DIM + k];
        g_c[j] = c;
    }
}

// packed f32x2 FMA (Blackwell; only reachable via PTX)
__device__ __forceinline__ unsigned long long ffma2(unsigned long long a,
                                                    unsigned long long b,
                                                    unsigned long long c)
{
    unsigned long long d;
    asm("fma.rn.f32x2 %0, %1, %2, %3;" : "=l"(d) : "l"(a), "l"(b), "l"(c));
    return d;
}

// ---------------------------------------------------------------------------
// PER-WARP private cp.async pipelines — no __syncthreads anywhere in the
// main loop. Each warp owns 3 x 32-row smem buffers and its own commit/wait
// group stream; buffer reuse is same-warp program-ordered, so the only sync
// needed is __syncwarp (cross-lane visibility of each other's cp.async data
// and LDS reads). 24 warps/SM drift independently, smoothing DRAM demand
// that R16's block-wide barriers convoyed into a 56% duty cycle.
// Compute: 8 threads/row x 2 output cols, weights in 32 regs, smem reads
// broadcast within 8-lane groups, 80B row stride = conflict-free.
// ---------------------------------------------------------------------------
__global__ void __launch_bounds__(256, 3)
matvec_kernel(const float* __restrict__ chem, float* __restrict__ out, int rows)
{
    extern __shared__ __align__(16) float smem[];

    const int lane = threadIdx.x & 31;
    const int wid  = threadIdx.x >> 5;
    float* wbase   = smem + wid * (NBUF * TWORDS_W);

    const int ntiles = rows / TROWS_W;                       // 65536
    const int t0   = (blockIdx.x * WARPS_PER_BLOCK + wid) * TILES_PER_WARP;
    const int tend = (t0 + TILES_PER_WARP < ntiles) ? t0 + TILES_PER_WARP
                                                    : ntiles;

    // ---- stage one 32-row tile (2KB) into buffer b: 4 cp.async per lane ----
    auto issue_load = [&](int b, int tt) {
        const char* gbase = reinterpret_cast<const char*>(chem) +
                            (size_t)tt * (TROWS_W * DIM * 4);
        float* sbase = wbase + b * TWORDS_W;
#pragma unroll
        for (int k = 0; k < 4; ++k) {
            const int c   = lane + k * 32;      // 16B chunk index, 0..127
            const int r   = c >> 2;             // row within tile
            const int sub = c & 3;              // 16B chunk within row
            const unsigned sa = (unsigned)
                __cvta_generic_to_shared(&sbase[r * ROW_WORDS + sub * 4]);
            asm volatile("cp.async.cg.shared.global [%0], [%1], 16;\n"
                         :: "r"(sa), "l"(gbase + (size_t)c * 16));
        }
    };

    // ---- prologue: two tiles in flight, then fetch weights ----
    if (t0 < tend) issue_load(0, t0);
    asm volatile("cp.async.commit_group;\n");
    if (t0 + 1 < tend) issue_load(1, t0 + 1);
    asm volatile("cp.async.commit_group;\n");

    const int e  = lane & 7;           // 8 threads per row
    const int jg = e * 2;              // this thread's 2 output columns
    unsigned long long w0[8], w1[8];
    {
        const unsigned long long* wp0 =
            reinterpret_cast<const unsigned long long*>(&g_M[(jg + 0) * DIM]);
        const unsigned long long* wp1 =
            reinterpret_cast<const unsigned long long*>(&g_M[(jg + 1) * DIM]);
#pragma unroll
        for (int i2 = 0; i2 < 8; ++i2) { w0[i2] = wp0[i2]; w1[i2] = wp1[i2]; }
    }
    const float c0 = g_c[jg + 0];
    const float c1 = g_c[jg + 1];

    const int r0 = lane >> 3;          // this lane's row within a pass (0..3)

    int buf = 0;
    for (int t = t0; t < tend; ++t) {
        // keep two loads streaming while computing this tile
        if (t + 2 < tend) issue_load((buf + 2) % NBUF, t + 2);
        asm volatile("cp.async.commit_group;\n");
        asm volatile("cp.async.wait_group 2;\n");   // tile t complete
        __syncwarp();                               // see other lanes' copies

        const float* sbase = wbase + buf * TWORDS_W;
        const size_t row_base = (size_t)t * TROWS_W;
#pragma unroll
        for (int p = 0; p < 8; ++p) {              // 4 rows per pass
            const int r = r0 + p * 4;
            const ulonglong2* sp =
                reinterpret_cast<const ulonglong2*>(&sbase[r * ROW_WORDS]);
            ulonglong2 a0 = sp[0];
            ulonglong2 a1 = sp[1];
            ulonglong2 a2 = sp[2];
            ulonglong2 a3 = sp[3];
            const unsigned long long ap[8] = {a0.x, a0.y, a1.x, a1.y,
                                              a2.x, a2.y, a3.x, a3.y};

            unsigned long long acc0 =
                (unsigned long long)__float_as_uint(c0);
            unsigned long long acc1 =
                (unsigned long long)__float_as_uint(c1);
#pragma unroll
            for (int i2 = 0; i2 < 8; ++i2) {
                acc0 = ffma2(ap[i2], w0[i2], acc0);
                acc1 = ffma2(ap[i2], w1[i2], acc1);
            }
            float2 res;
            res.x = __uint_as_float((unsigned int)acc0) +
                    __uint_as_float((unsigned int)(acc0 >> 32));
            res.y = __uint_as_float((unsigned int)acc1) +
                    __uint_as_float((unsigned int)(acc1 >> 32));

            // warp store: 4 consecutive rows x 64B = 256B contiguous
            reinterpret_cast<float2*>(out + (row_base + r) * DIM)[e] = res;
        }
        __syncwarp();   // all lanes done reading buf before it is refilled
        buf = (buf + 1) % NBUF;
    }
}

extern "C" void kernel_launch(void* const* d_in, const int* in_sizes, int n_in,
                              void* d_out, int out_size)
{
    // inputs: 0=fp_16 (UNUSED), 1=chem_16, 2=in_proj_weight, 3=in_proj_bias,
    //         4=out_proj_weight, 5=out_proj_bias
    const float* chem  = (const float*)d_in[1];
    const float* in_w  = (const float*)d_in[2];
    const float* in_b  = (const float*)d_in[3];
    const float* out_w = (const float*)d_in[4];
    const float* out_b = (const float*)d_in[5];
    float* out = (float*)d_out;

    const int rows = in_sizes[1] / DIM;   // 2,097,152

    static bool attr_set = false;
    if (!attr_set) {
        cudaFuncSetAttribute(matvec_kernel,
                             cudaFuncAttributeMaxDynamicSharedMemorySize,
                             SMEM_BYTES);
        attr_set = true;
    }

    prep_kernel<<<1, 256>>>(in_w, in_b, out_w, out_b);

    const int ntiles = rows / TROWS_W;                           // 65536
    const int blocks = ntiles / (WARPS_PER_BLOCK * TILES_PER_WARP); // 1024
    matvec_kernel<<<blocks, 256, SMEM_BYTES>>>(chem, out, rows);
}